// round 16
// baseline (speedup 1.0000x reference)
#include <cuda_runtime.h>
#include <cuda_fp16.h>
#include <cstdint>

// ---------------- problem constants ----------------
#define BB   8
#define EE   512
#define LL   8192
#define KS   5
#define LC   (LL - KS + 1)   // 8188
#define NB2  4094
#define NB3  2730
#define LOUT 4096

// ---------------- scratch ----------------
__device__ __align__(16) char g_W2[4 * 32 * 5 * 4096];
__device__ __align__(16) __half g_xt[(size_t)BB * 32 * LL * 16];
__device__ float g_y[(size_t)BB * EE * LL];
__device__ float g_spart[4 * BB * LL];
__device__ float g_att[BB * LL * 3];

// ---------------- helpers ----------------
__device__ __forceinline__ uint32_t smem_to_u32(const void* p) {
    uint32_t a;
    asm("{ .reg .u64 t; cvta.to.shared.u64 t, %1; cvt.u32.u64 %0, t; }" : "=r"(a) : "l"(p));
    return a;
}
__device__ __forceinline__ void cp16(uint32_t s, const void* g) {
    asm volatile("cp.async.cg.shared.global [%0], [%1], 16;" :: "r"(s), "l"(g));
}
__device__ __forceinline__ void cp16z(uint32_t s, const void* g, int sz) {
    asm volatile("cp.async.cg.shared.global [%0], [%1], 16, %2;" :: "r"(s), "l"(g), "r"(sz));
}
#define CP_COMMIT() asm volatile("cp.async.commit_group;")
#define CP_WAIT0()  asm volatile("cp.async.wait_group 0;" ::: "memory")

__device__ __forceinline__ void ldsm4(uint32_t* r, uint32_t addr) {
    asm volatile("ldmatrix.sync.aligned.m8n8.x4.shared.b16 {%0,%1,%2,%3}, [%4];"
        : "=r"(r[0]), "=r"(r[1]), "=r"(r[2]), "=r"(r[3]) : "r"(addr));
}
__device__ __forceinline__ void ldsm4t(uint32_t* r, uint32_t addr) {
    asm volatile("ldmatrix.sync.aligned.m8n8.x4.trans.shared.b16 {%0,%1,%2,%3}, [%4];"
        : "=r"(r[0]), "=r"(r[1]), "=r"(r[2]), "=r"(r[3]) : "r"(addr));
}
__device__ __forceinline__ void mma_fp16(float* d, const uint32_t* a, uint32_t b0, uint32_t b1) {
    asm volatile("mma.sync.aligned.m16n8k16.row.col.f32.f16.f16.f32 "
        "{%0,%1,%2,%3}, {%4,%5,%6,%7}, {%8,%9}, {%0,%1,%2,%3};"
        : "+f"(d[0]), "+f"(d[1]), "+f"(d[2]), "+f"(d[3])
        : "r"(a[0]), "r"(a[1]), "r"(a[2]), "r"(a[3]), "r"(b0), "r"(b1));
}

// ---------------- SMEM layout (occ-2 conv, 2-stage bigchunks of 32 channels) ----------------
#define WSTG 40960                    // 10 images x 4KB per bigchunk
#define WBUF(st) ((st) * WSTG)        // 0, 40960
#define XBASE   81920
#define XIMG    6528                  // 136 rows x 48B per 16-ch sub-chunk
#define XSTG    (2 * XIMG)            // 13056
#define XBUF(st) (XBASE + (st) * XSTG)
#define SC_OFF  108032                // 256-float score scratch
#define SMEM_TOTAL 109056

// ---------------- kernel: prep W -> swizzled fp16 images ----------------
__global__ void k_prepW(const float* __restrict__ W) {
    int o = blockIdx.x * 256 + threadIdx.x;
    int e = o & 127;
    int c = (o >> 7) & 15;
    int rest = o >> 11;
    int tap = rest % 5;
    int ec = rest / 5;
    int e_g = (ec >> 5) * 128 + e;
    int c_g = (ec & 31) * 16 + c;
    float w = W[((size_t)e_g * EE + c_g) * KS + tap];
    size_t base = ((size_t)ec * 5 + tap) * 4096;
    uint32_t off = c * 256 + (((e >> 3) ^ (c & 7)) << 4) + (e & 7) * 2;
    *(__half*)(g_W2 + base + off) = __float2half(w);
}

// ---------------- kernel: prep X -> chunk-blocked fp16 [b][ck][t][c16] ----------------
__global__ void k_prepX(const float* __restrict__ x) {
    __shared__ float tile[64][65];
    const int tid = threadIdx.x;
    const int b = blockIdx.z;
    const int c0 = blockIdx.y * 64;
    const int t0 = blockIdx.x * 64;

    const float* xp = x + ((size_t)b * EE + c0) * LL + t0;
    #pragma unroll
    for (int i = 0; i < 16; i++) {
        int idx = tid + i * 256;
        int r = idx >> 6;
        int cl = idx & 63;
        tile[r][cl] = xp[(size_t)r * LL + cl];
    }
    __syncthreads();

    #pragma unroll
    for (int i = 0; i < 8; i++) {
        int idx = tid + i * 256;
        int ci = idx >> 9;
        int sub = idx & 511;
        int t = sub >> 3;
        int cu = sub & 7;
        __half h0 = __float2half(tile[ci * 16 + 2 * cu][t]);
        __half h1 = __float2half(tile[ci * 16 + 2 * cu + 1][t]);
        uint32_t pk = (uint32_t)__half_as_ushort(h0) |
                      ((uint32_t)__half_as_ushort(h1) << 16);
        int ck = (c0 >> 4) + ci;
        uint32_t* outp = (uint32_t*)(g_xt + (((size_t)b * 32 + ck) * LL + t0 + t) * 16);
        outp[cu] = pk;
    }
}

__global__ void k_nop() {}

// ---------------- conv loads for one 32-channel bigchunk into stage st ----------------
__device__ __forceinline__ void load_big_async(uint32_t sb, int st,
                                               const char* __restrict__ wsrc_base,
                                               const __half* __restrict__ xtb,
                                               int bs, int t0, int tid) {
    const char* wsrc = wsrc_base + (size_t)bs * 10 * 4096;
    uint32_t wdst = sb + WBUF(st);
    #pragma unroll
    for (int k = 0; k < 20; k++)
        cp16(wdst + (uint32_t)(tid + k * 128) * 16, wsrc + (size_t)(tid + k * 128) * 16);
    #pragma unroll
    for (int ck = 0; ck < 2; ck++) {
        const __half* csrc = xtb + (size_t)(2 * bs + ck) * LL * 16;
        uint32_t xdst = sb + XBUF(st) + ck * XIMG;
        {
            int tg = t0 + tid;
            int sz = (tg < LL) ? 16 : 0;
            int tc = (tg < LL) ? tg : (LL - 1);
            const char* src = (const char*)(csrc + (size_t)tc * 16);
            uint32_t dst = xdst + (uint32_t)tid * 48;
            cp16z(dst, src, sz);
            cp16z(dst + 16, src + 16, sz);
        }
        if (tid < 8) {
            int r = 128 + tid;
            int tg = t0 + r;
            int sz = (tg < LL) ? 16 : 0;
            int tc = (tg < LL) ? tg : (LL - 1);
            const char* src = (const char*)(csrc + (size_t)tc * 16);
            uint32_t dst = xdst + (uint32_t)r * 48;
            cp16z(dst, src, sz);
            cp16z(dst + 16, src + 16, sz);
        }
    }
}

// ---------------- kernel: conv via fp16 mma.sync, CTA 128t x 128e, 4 warps, occ 2 ----------------
__global__ void __launch_bounds__(128, 2)
k_conv_mma(const float* __restrict__ bias, const float* __restrict__ score_w) {
    extern __shared__ __align__(128) char smem[];
    const uint32_t sb = smem_to_u32(smem);
    const int tid = threadIdx.x, wid = tid >> 5, lane = tid & 31;
    const int b = blockIdx.z;
    const int etile = blockIdx.y;
    const int e0g = etile * 128;
    const int t0 = blockIdx.x * 128;
    const int wt = wid >> 1;
    const int we = wid & 1;

    const __half* xtb = g_xt + (size_t)b * 32 * LL * 16;
    const char* wsrc_base = g_W2 + (size_t)etile * 32 * 5 * 4096;

    const int g = lane >> 3, i8 = lane & 7;
    const int a_row0 = wt * 64 + (g & 1) * 8 + i8;
    const uint32_t a_col = (uint32_t)(g >> 1) * 16;
    const int b_c = (g & 1) * 8 + i8;
    const int b_e0 = we * 64 + (g >> 1) * 8;
    uint32_t boff[4];
    #pragma unroll
    for (int eb = 0; eb < 4; eb++) {
        int be = b_e0 + eb * 16;
        boff[eb] = (uint32_t)b_c * 256 + ((((be) >> 3) ^ (b_c & 7)) << 4);
    }

    float acc[128];
    #pragma unroll
    for (int k = 0; k < 128; k++) acc[k] = 0.f;

    // ---- prologue: bigchunk 0 resident ----
    load_big_async(sb, 0, wsrc_base, xtb, 0, t0, tid);
    CP_COMMIT();
    CP_WAIT0();
    __syncthreads();

    for (int s = 0; s < 16; s++) {
        const int buf = s & 1;

        if (s + 1 < 16) {
            load_big_async(sb, buf ^ 1, wsrc_base, xtb, s + 1, t0, tid);
            CP_COMMIT();
        }

        // ---- compute bigchunk s: flattened u = (ck,tap) stream, fragment SW pipeline ----
        const uint32_t xb0 = sb + XBUF(buf);
        const uint32_t wb0 = sb + WBUF(buf);

        uint32_t ah[2][4][4];
        uint32_t bh[2][4];
        // preload u=0 (ck=0, tap=0)
        #pragma unroll
        for (int mf = 0; mf < 4; mf++)
            ldsm4(ah[0][mf], xb0 + (uint32_t)(a_row0 + mf * 16) * 48 + a_col);
        ldsm4t(bh[0], wb0 + boff[0]);

        #pragma unroll
        for (int u = 0; u < 10; u++) {
            const int cur = u & 1;
            const int tap  = (u < 5) ? u : (u - 5);
            const int tap1 = (u + 1 < 5) ? (u + 1) : (u + 1 - 5);
            const uint32_t wh  = wb0 + (uint32_t)(u >= 5 ? 20480 : 0) + (uint32_t)tap * 4096;
            const uint32_t wh1 = wb0 + (uint32_t)(u + 1 >= 5 ? 20480 : 0) + (uint32_t)tap1 * 4096;
            const uint32_t xh1 = xb0 + (uint32_t)(u + 1 >= 5 ? XIMG : 0);
            #pragma unroll
            for (int eb = 0; eb < 4; eb++) {
                const int bcur = eb & 1;
                // prefetch next B fragment (distance 1)
                if (eb < 3)       ldsm4t(bh[bcur ^ 1], wh + boff[eb + 1]);
                else if (u < 9)   ldsm4t(bh[bcur ^ 1], wh1 + boff[0]);
                // prefetch next A fragments at start of the eb stream
                if (eb == 0 && u < 9) {
                    #pragma unroll
                    for (int mf = 0; mf < 4; mf++)
                        ldsm4(ah[cur ^ 1][mf],
                              xh1 + (uint32_t)(a_row0 + mf * 16 + tap1) * 48 + a_col);
                }
                #pragma unroll
                for (int mf = 0; mf < 4; mf++) {
                    #pragma unroll
                    for (int sub = 0; sub < 2; sub++) {
                        float* D = acc + (mf * 8 + eb * 2 + sub) * 4;
                        mma_fp16(D, ah[cur][mf], bh[bcur][sub * 2], bh[bcur][sub * 2 + 1]);
                    }
                }
            }
        }

        if (s + 1 < 16) CP_WAIT0();
        __syncthreads();
    }

    // ---- epilogue: direct register->global stores + register score reduction ----
    const int eq = (lane & 3) << 1;      // 0,2,4,6
    const int tq = lane >> 2;            // 0..7
    float* scratch = (float*)(smem + SC_OFF);    // [2][128]
    float* sp = g_spart + (size_t)etile * (BB * LL) + (size_t)b * LL + t0;

    float sacc[8];
    #pragma unroll
    for (int i = 0; i < 8; i++) sacc[i] = 0.f;

    #pragma unroll
    for (int nf = 0; nf < 8; nf++) {
        const int e = e0g + we * 64 + nf * 8 + eq;
        const float b0 = __ldg(bias + e);
        const float b1 = __ldg(bias + e + 1);
        const float w0 = __ldg(score_w + e);
        const float w1 = __ldg(score_w + e + 1);
        float* y0 = g_y + ((size_t)b * EE + e) * LL;
        float* y1 = y0 + LL;
        #pragma unroll
        for (int mf = 0; mf < 4; mf++) {
            const float* A = acc + (mf * 8 + nf) * 4;
            const int t1 = t0 + wt * 64 + mf * 16 + tq;
            const int t2 = t1 + 8;
            const bool ok1 = t1 < LC;
            const bool ok2 = t2 < LC;
            float v0 = ok1 ? A[0] + b0 : 0.f;
            float v1 = ok1 ? A[1] + b1 : 0.f;
            float v2 = ok2 ? A[2] + b0 : 0.f;
            float v3 = ok2 ? A[3] + b1 : 0.f;
            y0[t1] = v0;
            y1[t1] = v1;
            y0[t2] = v2;
            y1[t2] = v3;
            sacc[mf * 2]     += v0 * w0 + v1 * w1;
            sacc[mf * 2 + 1] += v2 * w0 + v3 * w1;
        }
    }
    #pragma unroll
    for (int i = 0; i < 8; i++) {
        sacc[i] += __shfl_xor_sync(0xffffffff, sacc[i], 1);
        sacc[i] += __shfl_xor_sync(0xffffffff, sacc[i], 2);
    }
    if ((lane & 3) == 0) {
        #pragma unroll
        for (int mf = 0; mf < 4; mf++) {
            #pragma unroll
            for (int r = 0; r < 2; r++)
                scratch[we * 128 + wt * 64 + mf * 16 + r * 8 + tq] = sacc[mf * 2 + r];
        }
    }
    __syncthreads();
    if (tid < 128) sp[tid] = scratch[tid] + scratch[128 + tid];
}

// ---------------- kernel: fused score reduce + softmax over 3 widths ----------------
// grid (LL/256, BB), block 256
__global__ void k_att() {
    __shared__ float ss[264];            // s for t in [t0-2, t0+261]
    const int b = blockIdx.y;
    const int t0 = blockIdx.x * 256;
    const int tid = threadIdx.x;

    for (int i = tid; i < 264; i += 256) {
        int t = t0 - 2 + i;
        float v = 0.f;
        if (t >= 0 && t < LL) {
            size_t idx = (size_t)b * LL + t;
            v = (g_spart[idx] + g_spart[(size_t)BB * LL + idx]) +
                (g_spart[2 * (size_t)BB * LL + idx] + g_spart[3 * (size_t)BB * LL + idx]);
        }
        ss[i] = v;
    }
    __syncthreads();

    const int t = t0 + tid;
    float sc1 = (t < LC) ? ss[tid + 2] : 0.f;
    int n2 = t >> 1;
    int l2 = 2 * n2 - t0 + 2;
    float sc2 = (n2 < NB2) ? 0.5f * (ss[l2] + ss[l2 + 1]) : 0.f;
    int n3 = t / 3;
    int l3 = 3 * n3 - t0 + 2;
    float sc3 = (n3 < NB3) ? (ss[l3] + ss[l3 + 1] + ss[l3 + 2]) * (1.f / 3.f) : 0.f;
    float m  = fmaxf(sc1, fmaxf(sc2, sc3));
    float e1 = expf(sc1 - m);
    float e2 = expf(sc2 - m);
    float e3 = expf(sc3 - m);
    float inv = 1.f / (e1 + e2 + e3);
    float* ap = g_att + ((size_t)b * LL + t) * 3;
    ap[0] = e1 * inv;
    ap[1] = e2 * inv;
    ap[2] = e3 * inv;
}

// ---------------- kernel: blend widths + downsample ----------------
// grid (LOUT/128, EE/64, BB), block 256: 128 td x 2 e-par, 32 e/thread
__global__ void k_combine(float* __restrict__ out) {
    __shared__ float satt[768];
    const int tid = threadIdx.x;
    const int b = blockIdx.z;
    const int e0 = blockIdx.y * 64;
    const int tdblk = blockIdx.x;
    const int tbase = tdblk * 256;
    const float* ag = g_att + ((size_t)b * LL + tbase) * 3;
    for (int i = tid; i < 768; i += 256) satt[i] = ag[i];
    __syncthreads();

    const int tdl = tid & 127;
    const int td = tdblk * 128 + tdl;
    const int baseg = td * 2;
    const int basel = tdl * 2;

    const float a0 = satt[basel * 3 + 0], a1 = satt[basel * 3 + 1], a2 = satt[basel * 3 + 2];
    const float a3 = satt[basel * 3 + 3], a4 = satt[basel * 3 + 4], a5 = satt[basel * 3 + 5];

    const int r = baseg % 3;
    const bool ok3_0 = (baseg / 3) < NB3;
    const bool ok3_1 = ((baseg + 1) / 3) < NB3;
    const bool ok2 = td < NB2;

    for (int i = 0; i < 32; i++) {
        const int e = e0 + (tid >> 7) + 2 * i;
        const float* yrow = g_y + ((size_t)b * EE + e) * LL;
        float w[6];
        #pragma unroll
        for (int d = 0; d < 6; d++) {
            int idx = baseg + d - 2;
            w[d] = (idx >= 0 && idx < LL) ? yrow[idx] : 0.f;
        }
        float v1_0 = w[2];
        float v1_1 = w[3];
        float v2   = ok2 ? 0.5f * (w[2] + w[3]) : 0.f;

        float p0 = w[0] + w[1] + w[2];
        float p1 = w[1] + w[2] + w[3];
        float p2 = w[2] + w[3] + w[4];
        float p3 = w[3] + w[4] + w[5];
        float s0 = (r == 0) ? p2 : ((r == 1) ? p1 : p0);
        float s1 = (r == 0) ? p2 : ((r == 1) ? p1 : p3);
        float v3_0 = ok3_0 ? s0 * (1.f / 3.f) : 0.f;
        float v3_1 = ok3_1 ? s1 * (1.f / 3.f) : 0.f;

        out[((size_t)b * EE + e) * LOUT + td] =
            0.5f * (a0 * v1_0 + a1 * v2 + a2 * v3_0 +
                    a3 * v1_1 + a4 * v2 + a5 * v3_1);
    }
}

// ---------------- launcher ----------------
extern "C" void kernel_launch(void* const* d_in, const int* in_sizes, int n_in,
                              void* d_out, int out_size) {
    const float* x       = (const float*)d_in[0];
    const float* conv_w  = (const float*)d_in[1];
    const float* conv_b  = (const float*)d_in[2];
    const float* score_w = (const float*)d_in[3];
    float* out = (float*)d_out;

    cudaFuncSetAttribute(k_conv_mma, cudaFuncAttributeMaxDynamicSharedMemorySize, SMEM_TOTAL);

    k_prepW<<<5120, 256>>>(conv_w);
    k_prepX<<<dim3(LL / 64, EE / 64, BB), 256>>>(x);

    // profiler captures the 4th launch -> keep the conv there
    k_nop<<<1, 32>>>();

    dim3 cg(LL / 128, 4, BB);
    k_conv_mma<<<cg, 128, SMEM_TOTAL>>>(conv_b, score_w);

    k_att<<<dim3(LL / 256, BB), 256>>>();
    k_combine<<<dim3(LOUT / 128, EE / 64, BB), 256>>>(out);
}